// round 2
// baseline (speedup 1.0000x reference)
#include <cuda_runtime.h>
#include <math.h>

#define Bv   4
#define Tn   2048
#define Cn   384
#define Hn   6
#define HSn  64
#define BTn  8192
#define BHn  24
#define C4n  1536

// ------------------------- scratch (static device globals) -------------------------
__device__ float g_h[BTn * Cn];                      // LN output (reused for LN1 and LN2)
__device__ float g_q[BHn * Tn * HSn];
__device__ float g_k[BHn * Tn * HSn];
__device__ float g_v[BHn * Tn * HSn];
__device__ float g_s[(size_t)BHn * Tn * Tn];         // scores transposed: [bh][s][t]  (403MB)
__device__ float g_attn[BTn * Cn];                   // attention output, head-merged [bt][c]
__device__ float g_x1[BTn * Cn];                     // residual-1 output
__device__ float g_f1[BTn * C4n];                    // MLP hidden

// ------------------------- helpers -------------------------
#define FMA16(A4, B4)                                          \
  do {                                                         \
    acc[0][0] = fmaf(A4.x, B4.x, acc[0][0]);                   \
    acc[0][1] = fmaf(A4.x, B4.y, acc[0][1]);                   \
    acc[0][2] = fmaf(A4.x, B4.z, acc[0][2]);                   \
    acc[0][3] = fmaf(A4.x, B4.w, acc[0][3]);                   \
    acc[1][0] = fmaf(A4.y, B4.x, acc[1][0]);                   \
    acc[1][1] = fmaf(A4.y, B4.y, acc[1][1]);                   \
    acc[1][2] = fmaf(A4.y, B4.z, acc[1][2]);                   \
    acc[1][3] = fmaf(A4.y, B4.w, acc[1][3]);                   \
    acc[2][0] = fmaf(A4.z, B4.x, acc[2][0]);                   \
    acc[2][1] = fmaf(A4.z, B4.y, acc[2][1]);                   \
    acc[2][2] = fmaf(A4.z, B4.z, acc[2][2]);                   \
    acc[2][3] = fmaf(A4.z, B4.w, acc[2][3]);                   \
    acc[3][0] = fmaf(A4.w, B4.x, acc[3][0]);                   \
    acc[3][1] = fmaf(A4.w, B4.y, acc[3][1]);                   \
    acc[3][2] = fmaf(A4.w, B4.z, acc[3][2]);                   \
    acc[3][3] = fmaf(A4.w, B4.w, acc[3][3]);                   \
  } while (0)

// ------------------------- LayerNorm: one block per row (C=384, 128 threads) -------------------------
__global__ void ln_kernel(const float* __restrict__ in, const float* __restrict__ gamma,
                          const float* __restrict__ beta, float* __restrict__ out) {
    int row = blockIdx.x;
    int tid = threadIdx.x;
    const float* p = in + row * Cn;
    float v0 = p[tid], v1 = p[tid + 128], v2 = p[tid + 256];
    float s = v0 + v1 + v2;
    __shared__ float red[4];
    #pragma unroll
    for (int o = 16; o > 0; o >>= 1) s += __shfl_xor_sync(0xffffffffu, s, o);
    if ((tid & 31) == 0) red[tid >> 5] = s;
    __syncthreads();
    float mean = (red[0] + red[1] + red[2] + red[3]) * (1.0f / Cn);
    __syncthreads();
    float d0 = v0 - mean, d1 = v1 - mean, d2 = v2 - mean;
    float q = d0 * d0 + d1 * d1 + d2 * d2;
    #pragma unroll
    for (int o = 16; o > 0; o >>= 1) q += __shfl_xor_sync(0xffffffffu, q, o);
    if ((tid & 31) == 0) red[tid >> 5] = q;
    __syncthreads();
    float var = (red[0] + red[1] + red[2] + red[3]) * (1.0f / Cn);
    float r = rsqrtf(var + 1e-5f);
    float* o = out + row * Cn;
    o[tid]       = d0 * r * gamma[tid]       + beta[tid];
    o[tid + 128] = d1 * r * gamma[tid + 128] + beta[tid + 128];
    o[tid + 256] = d2 * r * gamma[tid + 256] + beta[tid + 256];
}

// ------------------------- QKV projection -------------------------
// grid (BT/64, H, 3). Tile 64(bt) x 64(d), K=C=384.
__global__ void qkv_kernel(const float* __restrict__ wq, const float* __restrict__ wk,
                           const float* __restrict__ wv) {
    const float* W;
    float* O;
    int hh = blockIdx.y;
    if (blockIdx.z == 0)      { W = wq; O = g_q; }
    else if (blockIdx.z == 1) { W = wk; O = g_k; }
    else                      { W = wv; O = g_v; }
    W += hh * Cn * HSn;
    int m0 = blockIdx.x * 64;
    int tid = threadIdx.x, tx = tid & 15, ty = tid >> 4;
    __shared__ float As[16][68];
    __shared__ float Bs[16][64];
    float acc[4][4] = {};
    for (int k0 = 0; k0 < Cn; k0 += 16) {
        #pragma unroll
        for (int i = 0; i < 4; i++) {
            int idx = tid + i * 256;
            int m = idx >> 4, k = idx & 15;
            As[k][m] = g_h[(m0 + m) * Cn + k0 + k];
        }
        #pragma unroll
        for (int i = 0; i < 4; i++) {
            int idx = tid + i * 256;
            int k = idx >> 6, n = idx & 63;
            Bs[k][n] = W[(k0 + k) * HSn + n];
        }
        __syncthreads();
        #pragma unroll
        for (int kk = 0; kk < 16; kk++) {
            float4 a = *(const float4*)&As[kk][ty * 4];
            float4 b = *(const float4*)&Bs[kk][tx * 4];
            FMA16(a, b);
        }
        __syncthreads();
    }
    #pragma unroll
    for (int i = 0; i < 4; i++) {
        int bt = m0 + ty * 4 + i;
        int b = bt >> 11, t = bt & (Tn - 1);
        float* o = O + (((size_t)(b * Hn + hh) * Tn + t) * HSn) + tx * 4;
        o[0] = acc[i][0]; o[1] = acc[i][1]; o[2] = acc[i][2]; o[3] = acc[i][3];
    }
}

// ------------------------- Scores (transposed): S[bh][s][t] = scale * K[s]·Q[t] -------------------------
// grid (tTiles=32, sTiles=32, bh=24). Fully masked tiles (tTile < sTile) skipped.
__global__ void score_kernel() {
    int tT = blockIdx.x, sT = blockIdx.y, bh = blockIdx.z;
    if (tT < sT) return;
    const float* Kp = g_k + (size_t)bh * Tn * HSn;
    const float* Qp = g_q + (size_t)bh * Tn * HSn;
    int s0 = sT * 64, t0 = tT * 64;
    int tid = threadIdx.x, tx = tid & 15, ty = tid >> 4;
    __shared__ float Kt[64][68];   // [d][s]
    __shared__ float Qt[64][68];   // [d][t]
    #pragma unroll
    for (int i = 0; i < 16; i++) {
        int idx = tid + i * 256;
        int r = idx >> 6, d = idx & 63;
        Kt[d][r] = Kp[(s0 + r) * HSn + d];
        Qt[d][r] = Qp[(t0 + r) * HSn + d];
    }
    __syncthreads();
    float acc[4][4] = {};
    #pragma unroll 16
    for (int dd = 0; dd < 64; dd++) {
        float4 a = *(const float4*)&Kt[dd][ty * 4];
        float4 b = *(const float4*)&Qt[dd][tx * 4];
        FMA16(a, b);
    }
    const float scale = 0.05103103630798287f;  // 384^-0.5
    float* Sp = g_s + (size_t)bh * Tn * Tn;
    #pragma unroll
    for (int i = 0; i < 4; i++) {
        float* row = Sp + (size_t)(s0 + ty * 4 + i) * Tn + t0 + tx * 4;
        row[0] = acc[i][0] * scale;
        row[1] = acc[i][1] * scale;
        row[2] = acc[i][2] * scale;
        row[3] = acc[i][3] * scale;
    }
}

// ------------------------- Per-key softmax over query axis (contiguous t), in place -------------------------
// grid (BH*T). Valid region t in [s, T); masked region written 0.
__global__ void softmax_kernel() {
    int row = blockIdx.x;            // bh*T + s
    int s = row & (Tn - 1);
    float* p = g_s + (size_t)row * Tn;
    __shared__ float buf[Tn];
    __shared__ float red[8];
    int tid = threadIdx.x;
    float m = -3.0e38f;
    for (int t = tid; t < Tn; t += 256) {
        float v = (t >= s) ? p[t] : -3.0e38f;
        buf[t] = v;
        m = fmaxf(m, v);
    }
    #pragma unroll
    for (int o = 16; o > 0; o >>= 1) m = fmaxf(m, __shfl_xor_sync(0xffffffffu, m, o));
    if ((tid & 31) == 0) red[tid >> 5] = m;
    __syncthreads();
    m = red[0];
    #pragma unroll
    for (int w = 1; w < 8; w++) m = fmaxf(m, red[w]);
    float Z = 0.f;
    for (int t = tid; t < Tn; t += 256) {
        if (t >= s) {
            float e = __expf(buf[t] - m);
            buf[t] = e;
            Z += e;
        }
    }
    #pragma unroll
    for (int o = 16; o > 0; o >>= 1) Z += __shfl_xor_sync(0xffffffffu, Z, o);
    __syncthreads();
    if ((tid & 31) == 0) red[tid >> 5] = Z;
    __syncthreads();
    Z = red[0] + red[1] + red[2] + red[3] + red[4] + red[5] + red[6] + red[7];
    float inv = 1.0f / Z;
    for (int t = tid; t < Tn; t += 256) p[t] = (t >= s) ? buf[t] * inv : 0.0f;
}

// ------------------------- AV: out[t,d] = sum_s W[s,t] * V[s,d], head-merged write -------------------------
// grid (tTiles=32, bh=24). s loop only up to diagonal (rest is exactly zero).
__global__ void av_kernel() {
    int tT = blockIdx.x, bh = blockIdx.y;
    int b = bh / Hn, hh = bh % Hn;
    const float* Wp = g_s + (size_t)bh * Tn * Tn;
    const float* Vp = g_v + (size_t)bh * Tn * HSn;
    int t0 = tT * 64;
    int tid = threadIdx.x, tx = tid & 15, ty = tid >> 4;
    __shared__ float Ws[16][68];   // [s][t]
    __shared__ float Vs[16][64];   // [s][d]
    float acc[4][4] = {};
    int nS = (tT + 1) * 4;          // s-tiles of 16, covering s <= t_max
    for (int st = 0; st < nS; st++) {
        int s0 = st * 16;
        #pragma unroll
        for (int i = 0; i < 4; i++) {
            int idx = tid + i * 256;
            int k = idx >> 6, n = idx & 63;
            Ws[k][n] = Wp[(size_t)(s0 + k) * Tn + t0 + n];
            Vs[k][n] = Vp[(s0 + k) * HSn + n];
        }
        __syncthreads();
        #pragma unroll
        for (int kk = 0; kk < 16; kk++) {
            float4 a = *(const float4*)&Ws[kk][ty * 4];
            float4 b = *(const float4*)&Vs[kk][tx * 4];
            FMA16(a, b);
        }
        __syncthreads();
    }
    #pragma unroll
    for (int i = 0; i < 4; i++) {
        int t = t0 + ty * 4 + i;
        float* o = g_attn + ((size_t)(b * Tn + t)) * Cn + hh * HSn + tx * 4;
        o[0] = acc[i][0]; o[1] = acc[i][1]; o[2] = acc[i][2]; o[3] = acc[i][3];
    }
}

// ------------------------- Generic [BT,K] @ [K,N] GEMM with epilogue -------------------------
// EPI 0: bias + relu.   EPI 1: bias + residual (resid is [BT,N], N==C).
template <int EPI>
__global__ void gemm_bt(const float* __restrict__ A, const float* __restrict__ Bw,
                        const float* __restrict__ bias, const float* __restrict__ resid,
                        float* __restrict__ Co, int N, int K) {
    int n0 = blockIdx.x * 64, m0 = blockIdx.y * 64;
    int tid = threadIdx.x, tx = tid & 15, ty = tid >> 4;
    __shared__ float As[16][68];
    __shared__ float Bs[16][64];
    float acc[4][4] = {};
    for (int k0 = 0; k0 < K; k0 += 16) {
        #pragma unroll
        for (int i = 0; i < 4; i++) {
            int idx = tid + i * 256;
            int m = idx >> 4, k = idx & 15;
            As[k][m] = A[(m0 + m) * K + k0 + k];
        }
        #pragma unroll
        for (int i = 0; i < 4; i++) {
            int idx = tid + i * 256;
            int k = idx >> 6, n = idx & 63;
            Bs[k][n] = Bw[(k0 + k) * N + n0 + n];
        }
        __syncthreads();
        #pragma unroll
        for (int kk = 0; kk < 16; kk++) {
            float4 a = *(const float4*)&As[kk][ty * 4];
            float4 b = *(const float4*)&Bs[kk][tx * 4];
            FMA16(a, b);
        }
        __syncthreads();
    }
    #pragma unroll
    for (int i = 0; i < 4; i++) {
        int m = m0 + ty * 4 + i;
        #pragma unroll
        for (int j = 0; j < 4; j++) {
            int n = n0 + tx * 4 + j;
            float v = acc[i][j] + bias[n];
            if (EPI == 0) v = fmaxf(v, 0.0f);
            else          v += resid[(size_t)m * N + n];
            Co[(size_t)m * N + n] = v;
        }
    }
}

// ------------------------- launch -------------------------
extern "C" void kernel_launch(void* const* d_in, const int* in_sizes, int n_in,
                              void* d_out, int out_size) {
    const float* x      = (const float*)d_in[0];
    const float* wq     = (const float*)d_in[1];
    const float* wk     = (const float*)d_in[2];
    const float* wv     = (const float*)d_in[3];
    const float* w_proj = (const float*)d_in[4];
    const float* b_proj = (const float*)d_in[5];
    const float* w1     = (const float*)d_in[6];
    const float* b1     = (const float*)d_in[7];
    const float* w2     = (const float*)d_in[8];
    const float* b2     = (const float*)d_in[9];
    const float* g1     = (const float*)d_in[10];
    const float* be1    = (const float*)d_in[11];
    const float* g2     = (const float*)d_in[12];
    const float* be2    = (const float*)d_in[13];
    float* out = (float*)d_out;

    float *p_h, *p_x1, *p_attn, *p_f1;
    cudaGetSymbolAddress((void**)&p_h,    g_h);
    cudaGetSymbolAddress((void**)&p_x1,   g_x1);
    cudaGetSymbolAddress((void**)&p_attn, g_attn);
    cudaGetSymbolAddress((void**)&p_f1,   g_f1);

    // 1. LN1
    ln_kernel<<<BTn, 128>>>(x, g1, be1, p_h);
    // 2. QKV projections
    qkv_kernel<<<dim3(BTn / 64, Hn, 3), 256>>>(wq, wk, wv);
    // 3. Scores (transposed, causal-skip)
    score_kernel<<<dim3(Tn / 64, Tn / 64, BHn), 256>>>();
    // 4. Per-key softmax over query axis
    softmax_kernel<<<BHn * Tn, 256>>>();
    // 5. AV + head merge
    av_kernel<<<dim3(Tn / 64, BHn), 256>>>();
    // 6. Output projection + residual 1
    gemm_bt<1><<<dim3(Cn / 64, BTn / 64), 256>>>(p_attn, w_proj, b_proj, x, p_x1, Cn, Cn);
    // 7. LN2
    ln_kernel<<<BTn, 128>>>(p_x1, g2, be2, p_h);
    // 8. MLP up + relu
    gemm_bt<0><<<dim3(C4n / 64, BTn / 64), 256>>>(p_h, w1, b1, nullptr, p_f1, C4n, Cn);
    // 9. MLP down + residual 2 -> out
    gemm_bt<1><<<dim3(Cn / 64, BTn / 64), 256>>>(p_f1, w2, b2, p_x1, out, Cn, C4n);
}

// round 3
// speedup vs baseline: 2.1123x; 2.1123x over previous
#include <cuda_runtime.h>
#include <math.h>

#define Bv   4
#define Tn   2048
#define Cn   384
#define Hn   6
#define HSn  64
#define BTn  8192
#define BHn  24
#define C4n  1536

// ------------------------- scratch (static device globals) -------------------------
__device__ float g_h[BTn * Cn];
__device__ float g_q[BHn * Tn * HSn];
__device__ float g_k[BHn * Tn * HSn];
__device__ float g_v[BHn * Tn * HSn];
__device__ float g_s[(size_t)BHn * Tn * Tn];   // scores transposed: [bh][s][t]
__device__ float g_attn[BTn * Cn];
__device__ float g_x1[BTn * Cn];
__device__ float g_f1[BTn * C4n];

// ------------------------- tf32 mma helpers -------------------------
__device__ __forceinline__ float tf32r(float x) {
    unsigned u;
    asm("cvt.rna.tf32.f32 %0, %1;" : "=r"(u) : "f"(x));
    return __uint_as_float(u);
}

__device__ __forceinline__ void mma8(float* c, const unsigned* a, const unsigned* b) {
    asm volatile(
        "mma.sync.aligned.m16n8k8.row.col.f32.tf32.tf32.f32 "
        "{%0,%1,%2,%3}, {%4,%5,%6,%7}, {%8,%9}, {%0,%1,%2,%3};\n"
        : "+f"(c[0]), "+f"(c[1]), "+f"(c[2]), "+f"(c[3])
        : "r"(a[0]), "r"(a[1]), "r"(a[2]), "r"(a[3]), "r"(b[0]), "r"(b[1]));
}

// ------------------------- LayerNorm -------------------------
__global__ void ln_kernel(const float* __restrict__ in, const float* __restrict__ gamma,
                          const float* __restrict__ beta, float* __restrict__ out) {
    int row = blockIdx.x;
    int tid = threadIdx.x;
    const float* p = in + row * Cn;
    float v0 = p[tid], v1 = p[tid + 128], v2 = p[tid + 256];
    float s = v0 + v1 + v2;
    __shared__ float red[4];
    #pragma unroll
    for (int o = 16; o > 0; o >>= 1) s += __shfl_xor_sync(0xffffffffu, s, o);
    if ((tid & 31) == 0) red[tid >> 5] = s;
    __syncthreads();
    float mean = (red[0] + red[1] + red[2] + red[3]) * (1.0f / Cn);
    __syncthreads();
    float d0 = v0 - mean, d1 = v1 - mean, d2 = v2 - mean;
    float q = d0 * d0 + d1 * d1 + d2 * d2;
    #pragma unroll
    for (int o = 16; o > 0; o >>= 1) q += __shfl_xor_sync(0xffffffffu, q, o);
    if ((tid & 31) == 0) red[tid >> 5] = q;
    __syncthreads();
    float var = (red[0] + red[1] + red[2] + red[3]) * (1.0f / Cn);
    float r = rsqrtf(var + 1e-5f);
    float* o = out + row * Cn;
    o[tid]       = d0 * r * gamma[tid]       + beta[tid];
    o[tid + 128] = d1 * r * gamma[tid + 128] + beta[tid + 128];
    o[tid + 256] = d2 * r * gamma[tid + 256] + beta[tid + 256];
}

// ------------------------- generic GEMM (tf32 mma): C[M,N] = A[M,K] @ B[K,N] -------------------------
// block tile 128x64, BK=32, 256 threads, 8 warps (4m x 2n), warp tile 32x32.
// EPI 0: bias+relu.  EPI 1: bias+resid.
template <int EPI>
__global__ __launch_bounds__(256)
void gemm_mma(const float* __restrict__ A, const float* __restrict__ Bw,
              const float* __restrict__ bias, const float* __restrict__ resid,
              float* __restrict__ Co, int N, int K) {
    __shared__ float As[128][36];   // [m][k], stride 36 (≡4 mod 32)
    __shared__ float Bs[32][68];    // [k][n], stride 68 (≡4 mod 32)
    int m0 = blockIdx.y * 128, n0 = blockIdx.x * 64;
    int tid = threadIdx.x, l = tid & 31, w = tid >> 5;
    int wm = (w & 3) * 32, wn = (w >> 2) * 32;
    int g = l >> 2, tg = l & 3;
    float acc[2][4][4] = {};
    for (int k0 = 0; k0 < K; k0 += 32) {
        #pragma unroll
        for (int i = 0; i < 4; i++) {
            int idx = tid + i * 256;
            int m = idx >> 3, kv = (idx & 7) * 4;
            float4 v = *(const float4*)&A[(size_t)(m0 + m) * K + k0 + kv];
            As[m][kv + 0] = tf32r(v.x); As[m][kv + 1] = tf32r(v.y);
            As[m][kv + 2] = tf32r(v.z); As[m][kv + 3] = tf32r(v.w);
        }
        #pragma unroll
        for (int i = 0; i < 2; i++) {
            int idx = tid + i * 256;
            int k = idx >> 4, nv = (idx & 15) * 4;
            float4 v = *(const float4*)&Bw[(size_t)(k0 + k) * N + n0 + nv];
            Bs[k][nv + 0] = tf32r(v.x); Bs[k][nv + 1] = tf32r(v.y);
            Bs[k][nv + 2] = tf32r(v.z); Bs[k][nv + 3] = tf32r(v.w);
        }
        __syncthreads();
        #pragma unroll
        for (int kk = 0; kk < 32; kk += 8) {
            unsigned a[2][4], b[4][2];
            #pragma unroll
            for (int im = 0; im < 2; im++) {
                int r = wm + im * 16;
                a[im][0] = __float_as_uint(As[r + g][kk + tg]);
                a[im][1] = __float_as_uint(As[r + 8 + g][kk + tg]);
                a[im][2] = __float_as_uint(As[r + g][kk + 4 + tg]);
                a[im][3] = __float_as_uint(As[r + 8 + g][kk + 4 + tg]);
            }
            #pragma unroll
            for (int jn = 0; jn < 4; jn++) {
                int c = wn + jn * 8;
                b[jn][0] = __float_as_uint(Bs[kk + tg][c + g]);
                b[jn][1] = __float_as_uint(Bs[kk + 4 + tg][c + g]);
            }
            #pragma unroll
            for (int im = 0; im < 2; im++)
                #pragma unroll
                for (int jn = 0; jn < 4; jn++) mma8(acc[im][jn], a[im], b[jn]);
        }
        __syncthreads();
    }
    #pragma unroll
    for (int im = 0; im < 2; im++) {
        int r0 = m0 + wm + im * 16 + g;
        #pragma unroll
        for (int jn = 0; jn < 4; jn++) {
            int c = n0 + wn + jn * 8 + tg * 2;
            float b0v = bias[c], b1v = bias[c + 1];
            float v00 = acc[im][jn][0] + b0v, v01 = acc[im][jn][1] + b1v;
            float v10 = acc[im][jn][2] + b0v, v11 = acc[im][jn][3] + b1v;
            if (EPI == 0) {
                v00 = fmaxf(v00, 0.f); v01 = fmaxf(v01, 0.f);
                v10 = fmaxf(v10, 0.f); v11 = fmaxf(v11, 0.f);
            } else {
                v00 += resid[(size_t)r0 * N + c];     v01 += resid[(size_t)r0 * N + c + 1];
                v10 += resid[(size_t)(r0 + 8) * N + c]; v11 += resid[(size_t)(r0 + 8) * N + c + 1];
            }
            Co[(size_t)r0 * N + c] = v00;       Co[(size_t)r0 * N + c + 1] = v01;
            Co[(size_t)(r0 + 8) * N + c] = v10; Co[(size_t)(r0 + 8) * N + c + 1] = v11;
        }
    }
}

// ------------------------- QKV (tf32 mma): per (head, sel) GEMM [8192,384]@[384,64] -------------------------
__global__ __launch_bounds__(256)
void qkv_mma(const float* __restrict__ wq, const float* __restrict__ wk,
             const float* __restrict__ wv) {
    __shared__ float As[128][36];
    __shared__ float Bs[32][68];
    int hh = blockIdx.y;
    const float* W;
    float* O;
    if (blockIdx.z == 0)      { W = wq; O = g_q; }
    else if (blockIdx.z == 1) { W = wk; O = g_k; }
    else                      { W = wv; O = g_v; }
    W += hh * Cn * HSn;
    int m0 = blockIdx.x * 128;
    int tid = threadIdx.x, l = tid & 31, w = tid >> 5;
    int wm = (w & 3) * 32, wn = (w >> 2) * 32;
    int g = l >> 2, tg = l & 3;
    float acc[2][4][4] = {};
    for (int k0 = 0; k0 < Cn; k0 += 32) {
        #pragma unroll
        for (int i = 0; i < 4; i++) {
            int idx = tid + i * 256;
            int m = idx >> 3, kv = (idx & 7) * 4;
            float4 v = *(const float4*)&g_h[(size_t)(m0 + m) * Cn + k0 + kv];
            As[m][kv + 0] = tf32r(v.x); As[m][kv + 1] = tf32r(v.y);
            As[m][kv + 2] = tf32r(v.z); As[m][kv + 3] = tf32r(v.w);
        }
        {
            int idx = tid;          // 32x64 = 512 float4 / 256 threads = 2, unrolled
            #pragma unroll
            for (int i = 0; i < 2; i++) {
                int k = idx >> 4, nv = (idx & 15) * 4;
                float4 v = *(const float4*)&W[(size_t)(k0 + k) * HSn + nv];
                Bs[k][nv + 0] = tf32r(v.x); Bs[k][nv + 1] = tf32r(v.y);
                Bs[k][nv + 2] = tf32r(v.z); Bs[k][nv + 3] = tf32r(v.w);
                idx += 256;
            }
        }
        __syncthreads();
        #pragma unroll
        for (int kk = 0; kk < 32; kk += 8) {
            unsigned a[2][4], b[4][2];
            #pragma unroll
            for (int im = 0; im < 2; im++) {
                int r = wm + im * 16;
                a[im][0] = __float_as_uint(As[r + g][kk + tg]);
                a[im][1] = __float_as_uint(As[r + 8 + g][kk + tg]);
                a[im][2] = __float_as_uint(As[r + g][kk + 4 + tg]);
                a[im][3] = __float_as_uint(As[r + 8 + g][kk + 4 + tg]);
            }
            #pragma unroll
            for (int jn = 0; jn < 4; jn++) {
                int c = wn + jn * 8;
                b[jn][0] = __float_as_uint(Bs[kk + tg][c + g]);
                b[jn][1] = __float_as_uint(Bs[kk + 4 + tg][c + g]);
            }
            #pragma unroll
            for (int im = 0; im < 2; im++)
                #pragma unroll
                for (int jn = 0; jn < 4; jn++) mma8(acc[im][jn], a[im], b[jn]);
        }
        __syncthreads();
    }
    #pragma unroll
    for (int im = 0; im < 2; im++) {
        #pragma unroll
        for (int half = 0; half < 2; half++) {
            int m = m0 + wm + im * 16 + g + half * 8;
            int b = m >> 11, t = m & (Tn - 1);
            float* orow = O + (((size_t)(b * Hn + hh) * Tn + t) * HSn);
            #pragma unroll
            for (int jn = 0; jn < 4; jn++) {
                int c = wn + jn * 8 + tg * 2;
                orow[c]     = acc[im][jn][half * 2];
                orow[c + 1] = acc[im][jn][half * 2 + 1];
            }
        }
    }
}

// ------------------------- Scores (tf32 mma): S[bh][s][t], 128x128 tile, K=64 -------------------------
__global__ __launch_bounds__(256)
void score_mma() {
    extern __shared__ float sm[];
    float (*Ks)[68] = (float(*)[68])sm;             // [s][d]  (A, [m][k])
    float (*Qs)[68] = (float(*)[68])(sm + 128 * 68); // [t][d]  (B, [n][k])
    int tT = blockIdx.x, sT = blockIdx.y, bh = blockIdx.z;
    if (tT < sT) return;
    const float* Kp = g_k + (size_t)bh * Tn * HSn + (size_t)sT * 128 * HSn;
    const float* Qp = g_q + (size_t)bh * Tn * HSn + (size_t)tT * 128 * HSn;
    int tid = threadIdx.x, l = tid & 31, w = tid >> 5;
    int g = l >> 2, tg = l & 3;
    #pragma unroll
    for (int i = 0; i < 8; i++) {
        int idx = tid + i * 256;
        int r = idx >> 4, dv = (idx & 15) * 4;
        float4 a = *(const float4*)&Kp[(size_t)r * HSn + dv];
        float4 b = *(const float4*)&Qp[(size_t)r * HSn + dv];
        Ks[r][dv + 0] = tf32r(a.x); Ks[r][dv + 1] = tf32r(a.y);
        Ks[r][dv + 2] = tf32r(a.z); Ks[r][dv + 3] = tf32r(a.w);
        Qs[r][dv + 0] = tf32r(b.x); Qs[r][dv + 1] = tf32r(b.y);
        Qs[r][dv + 2] = tf32r(b.z); Qs[r][dv + 3] = tf32r(b.w);
    }
    __syncthreads();
    int wm = (w & 3) * 32, wn = (w >> 2) * 64;
    float acc[2][8][4] = {};
    #pragma unroll
    for (int kk = 0; kk < 64; kk += 8) {
        unsigned a[2][4], b[8][2];
        #pragma unroll
        for (int im = 0; im < 2; im++) {
            int r = wm + im * 16;
            a[im][0] = __float_as_uint(Ks[r + g][kk + tg]);
            a[im][1] = __float_as_uint(Ks[r + 8 + g][kk + tg]);
            a[im][2] = __float_as_uint(Ks[r + g][kk + 4 + tg]);
            a[im][3] = __float_as_uint(Ks[r + 8 + g][kk + 4 + tg]);
        }
        #pragma unroll
        for (int jn = 0; jn < 8; jn++) {
            int c = wn + jn * 8;
            b[jn][0] = __float_as_uint(Qs[c + g][kk + tg]);
            b[jn][1] = __float_as_uint(Qs[c + g][kk + 4 + tg]);
        }
        #pragma unroll
        for (int im = 0; im < 2; im++)
            #pragma unroll
            for (int jn = 0; jn < 8; jn++) mma8(acc[im][jn], a[im], b[jn]);
    }
    const float scale = 0.05103103630798287f;  // 384^-0.5
    float* Sp = g_s + (size_t)bh * Tn * Tn;
    #pragma unroll
    for (int im = 0; im < 2; im++) {
        #pragma unroll
        for (int half = 0; half < 2; half++) {
            int s = sT * 128 + wm + im * 16 + g + half * 8;
            float* row = Sp + (size_t)s * Tn + tT * 128;
            #pragma unroll
            for (int jn = 0; jn < 8; jn++) {
                int c = wn + jn * 8 + tg * 2;
                float2 v = make_float2(acc[im][jn][half * 2] * scale,
                                       acc[im][jn][half * 2 + 1] * scale);
                *(float2*)&row[c] = v;
            }
        }
    }
}

// ------------------------- per-key softmax over query axis, only t >= (s & ~127) -------------------------
__global__ void softmax_kernel() {
    int row = blockIdx.x;            // bh*T + s
    int s = row & (Tn - 1);
    int base = s & ~127;             // start of s's 128-tile: AV never reads t < base
    float* p = g_s + (size_t)row * Tn;
    __shared__ float buf[Tn];
    __shared__ float red[8];
    int tid = threadIdx.x;
    float m = -3.0e38f;
    for (int t = base + tid; t < Tn; t += 256) {
        float v = (t >= s) ? p[t] : -3.0e38f;
        buf[t] = v;
        m = fmaxf(m, v);
    }
    #pragma unroll
    for (int o = 16; o > 0; o >>= 1) m = fmaxf(m, __shfl_xor_sync(0xffffffffu, m, o));
    if ((tid & 31) == 0) red[tid >> 5] = m;
    __syncthreads();
    m = red[0];
    #pragma unroll
    for (int wv = 1; wv < 8; wv++) m = fmaxf(m, red[wv]);
    float Z = 0.f;
    for (int t = base + tid; t < Tn; t += 256) {
        if (t >= s) {
            float e = __expf(buf[t] - m);
            buf[t] = e;
            Z += e;
        }
    }
    #pragma unroll
    for (int o = 16; o > 0; o >>= 1) Z += __shfl_xor_sync(0xffffffffu, Z, o);
    __syncthreads();
    if ((tid & 31) == 0) red[tid >> 5] = Z;
    __syncthreads();
    Z = red[0] + red[1] + red[2] + red[3] + red[4] + red[5] + red[6] + red[7];
    float inv = 1.0f / Z;
    for (int t = base + tid; t < Tn; t += 256) p[t] = (t >= s) ? buf[t] * inv : 0.0f;
}

// ------------------------- AV (tf32 mma): D[d][t] = sum_s V[s][d] * W[s][t] -------------------------
// block: m=64 (d), n=128 (t); 8 warps (2m x 4n), warp tile 32x32; K loop s <= t-tile end.
__global__ __launch_bounds__(256)
void av_mma() {
    __shared__ float Vs[32][68];    // [s][d]  (A as [k][m])
    __shared__ float Ws[32][132];   // [s][t]  (B as [k][n])
    int tT = blockIdx.x, bh = blockIdx.y;
    int b = bh / Hn, h = bh % Hn;
    const float* Wp = g_s + (size_t)bh * Tn * Tn;
    const float* Vp = g_v + (size_t)bh * Tn * HSn;
    int t0 = tT * 128;
    int tid = threadIdx.x, l = tid & 31, w = tid >> 5;
    int g = l >> 2, tg = l & 3;
    int wm = (w & 1) * 32, wn = (w >> 1) * 32;
    float acc[2][4][4] = {};
    int sEnd = t0 + 128;
    for (int s0 = 0; s0 < sEnd; s0 += 32) {
        #pragma unroll
        for (int i = 0; i < 2; i++) {
            int idx = tid + i * 256;
            int k = idx >> 4, dv = (idx & 15) * 4;
            float4 v = *(const float4*)&Vp[(size_t)(s0 + k) * HSn + dv];
            Vs[k][dv + 0] = tf32r(v.x); Vs[k][dv + 1] = tf32r(v.y);
            Vs[k][dv + 2] = tf32r(v.z); Vs[k][dv + 3] = tf32r(v.w);
        }
        #pragma unroll
        for (int i = 0; i < 4; i++) {
            int idx = tid + i * 256;
            int k = idx >> 5, tv = (idx & 31) * 4;
            float4 v = *(const float4*)&Wp[(size_t)(s0 + k) * Tn + t0 + tv];
            Ws[k][tv + 0] = tf32r(v.x); Ws[k][tv + 1] = tf32r(v.y);
            Ws[k][tv + 2] = tf32r(v.z); Ws[k][tv + 3] = tf32r(v.w);
        }
        __syncthreads();
        #pragma unroll
        for (int kk = 0; kk < 32; kk += 8) {
            unsigned a[2][4], bfr[4][2];
            #pragma unroll
            for (int im = 0; im < 2; im++) {
                int r = wm + im * 16;
                a[im][0] = __float_as_uint(Vs[kk + tg][r + g]);
                a[im][1] = __float_as_uint(Vs[kk + tg][r + 8 + g]);
                a[im][2] = __float_as_uint(Vs[kk + 4 + tg][r + g]);
                a[im][3] = __float_as_uint(Vs[kk + 4 + tg][r + 8 + g]);
            }
            #pragma unroll
            for (int jn = 0; jn < 4; jn++) {
                int c = wn + jn * 8;
                bfr[jn][0] = __float_as_uint(Ws[kk + tg][c + g]);
                bfr[jn][1] = __float_as_uint(Ws[kk + 4 + tg][c + g]);
            }
            #pragma unroll
            for (int im = 0; im < 2; im++)
                #pragma unroll
                for (int jn = 0; jn < 4; jn++) mma8(acc[im][jn], a[im], bfr[jn]);
        }
        __syncthreads();
    }
    // write out^T: value at (d = wm+im*16+g(+8), t = wn+jn*8+tg*2(+1))
    #pragma unroll
    for (int im = 0; im < 2; im++) {
        #pragma unroll
        for (int half = 0; half < 2; half++) {
            int d = wm + im * 16 + g + half * 8;
            #pragma unroll
            for (int jn = 0; jn < 4; jn++) {
                int t = t0 + wn + jn * 8 + tg * 2;
                g_attn[(size_t)(b * Tn + t) * Cn + h * HSn + d]     = acc[im][jn][half * 2];
                g_attn[(size_t)(b * Tn + t + 1) * Cn + h * HSn + d] = acc[im][jn][half * 2 + 1];
            }
        }
    }
}

// ------------------------- launch -------------------------
extern "C" void kernel_launch(void* const* d_in, const int* in_sizes, int n_in,
                              void* d_out, int out_size) {
    const float* x      = (const float*)d_in[0];
    const float* wq     = (const float*)d_in[1];
    const float* wk     = (const float*)d_in[2];
    const float* wv     = (const float*)d_in[3];
    const float* w_proj = (const float*)d_in[4];
    const float* b_proj = (const float*)d_in[5];
    const float* w1     = (const float*)d_in[6];
    const float* b1     = (const float*)d_in[7];
    const float* w2     = (const float*)d_in[8];
    const float* b2     = (const float*)d_in[9];
    const float* g1     = (const float*)d_in[10];
    const float* be1    = (const float*)d_in[11];
    const float* g2     = (const float*)d_in[12];
    const float* be2    = (const float*)d_in[13];
    float* out = (float*)d_out;

    float *p_h, *p_x1, *p_attn, *p_f1;
    cudaGetSymbolAddress((void**)&p_h,    g_h);
    cudaGetSymbolAddress((void**)&p_x1,   g_x1);
    cudaGetSymbolAddress((void**)&p_attn, g_attn);
    cudaGetSymbolAddress((void**)&p_f1,   g_f1);

    cudaFuncSetAttribute(score_mma, cudaFuncAttributeMaxDynamicSharedMemorySize,
                         2 * 128 * 68 * (int)sizeof(float));

    // 1. LN1
    ln_kernel<<<BTn, 128>>>(x, g1, be1, p_h);
    // 2. QKV projections (tf32 mma)
    qkv_mma<<<dim3(BTn / 128, Hn, 3), 256>>>(wq, wk, wv);
    // 3. Scores (tf32 mma, 128x128 tiles, causal-skip)
    score_mma<<<dim3(Tn / 128, Tn / 128, BHn), 256, 2 * 128 * 68 * sizeof(float)>>>();
    // 4. Per-key softmax over query axis (tile-restricted)
    softmax_kernel<<<BHn * Tn, 256>>>();
    // 5. AV + head merge (tf32 mma, out^T formulation)
    av_mma<<<dim3(Tn / 128, BHn), 256>>>();
    // 6. Output projection + residual 1
    gemm_mma<1><<<dim3(Cn / 64, BTn / 128), 256>>>(p_attn, w_proj, b_proj, x, p_x1, Cn, Cn);
    // 7. LN2
    ln_kernel<<<BTn, 128>>>(p_x1, g2, be2, p_h);
    // 8. MLP up + relu
    gemm_mma<0><<<dim3(C4n / 64, BTn / 128), 256>>>(p_h, w1, b1, nullptr, p_f1, C4n, Cn);
    // 9. MLP down + residual 2 -> out
    gemm_mma<1><<<dim3(Cn / 64, BTn / 128), 256>>>(p_f1, w2, b2, p_x1, out, Cn, C4n);
}